// round 1
// baseline (speedup 1.0000x reference)
#include <cuda_runtime.h>
#include <cstdint>

// ---------------------------------------------------------------------------
// BaseProtonet: inv_d[N,P] = 1 / (||f-p||^2 / D + 1e-5),  labels[n] = proto_labels[argmax_p inv_d]
// N=262144, D=64, P=256.
// Strategy: register-tiled GEMM for the cross term using packed fp32x2 FMAs
// (fma.rn.f32x2, rt=1/SMSP vs 2 for scalar FFMA). Warp lanes span the proto
// dimension so feature-fragment smem reads are warp-broadcast (cheap), and
// features are stored as duplicated (a,a) pairs so the f32x2 broadcast operand
// needs no pack instructions in the inner loop.
// ---------------------------------------------------------------------------

#define EPSV 1e-5f

__device__ __forceinline__ unsigned long long ffma2(unsigned long long a,
                                                    unsigned long long b,
                                                    unsigned long long c) {
    unsigned long long d;
    asm("fma.rn.f32x2 %0, %1, %2, %3;" : "=l"(d) : "l"(a), "l"(b), "l"(c));
    return d;
}

constexpr int Dk = 64;    // feature dim
constexpr int Pn = 256;   // prototypes
constexpr int BM = 64;    // rows per block
constexpr int AS_STRIDE = 66;  // float2 units, padded (66*8 % 16 == 0 for LDS.128 align)

constexpr int SMEM_BS  = Pn * Dk * 4;            // 65536: protos transposed [k][p]
constexpr int SMEM_AS  = Dk * AS_STRIDE * 8;     // 33792: features dup-pairs [k][r]
constexpr int SMEM_P2  = Pn * 4;                 // 1024
constexpr int SMEM_F2  = BM * 4;                 // 256
constexpr int SMEM_BYTES = SMEM_BS + SMEM_AS + SMEM_P2 + SMEM_F2;  // 100608

__global__ void __launch_bounds__(256)
BaseProtonet_kernel(const float* __restrict__ features,
                    const float* __restrict__ protos,
                    const int*   __restrict__ proto_labels,
                    float* __restrict__ inv_out,
                    float* __restrict__ labels_out,
                    int labels_as_int)
{
    extern __shared__ char smem[];
    float*  Bs  = (float*)smem;                        // [Dk][Pn]
    float2* As2 = (float2*)(smem + SMEM_BS);           // [Dk][AS_STRIDE] (dup pairs)
    float*  p2s = (float*)(smem + SMEM_BS + SMEM_AS);  // [Pn]
    float*  f2s = p2s + Pn;                            // [BM]

    const int tid = threadIdx.x;      // 0..255
    const int tx  = tid & 31;         // lane: proto-group
    const int ty  = tid >> 5;         // warp: row-group

    // ---- Load prototypes transposed: thread t owns proto row t -------------
    {
        const float4* pp = (const float4*)(protos + tid * Dk);
        #pragma unroll
        for (int k4 = 0; k4 < Dk / 4; k4++) {
            float4 v = pp[k4];
            Bs[(k4 * 4 + 0) * Pn + tid] = v.x;
            Bs[(k4 * 4 + 1) * Pn + tid] = v.y;
            Bs[(k4 * 4 + 2) * Pn + tid] = v.z;
            Bs[(k4 * 4 + 3) * Pn + tid] = v.w;
        }
    }
    // ---- Load 64 feature rows, transposed + duplicated ---------------------
    {
        const float* fb = features + (size_t)blockIdx.x * BM * Dk;
        #pragma unroll
        for (int i = 0; i < (BM * Dk) / 256; i++) {
            int flat = tid + i * 256;          // coalesced gmem read
            int r = flat >> 6, k = flat & 63;
            float v = fb[flat];
            As2[k * AS_STRIDE + r] = make_float2(v, v);
        }
    }
    __syncthreads();

    // ---- Per-block norms ----------------------------------------------------
    if (tid < BM) {
        float s = 0.f;
        #pragma unroll
        for (int k = 0; k < Dk; k++) {
            float v = As2[k * AS_STRIDE + tid].x;
            s = fmaf(v, v, s);
        }
        f2s[tid] = s;
    }
    {
        float s = 0.f;
        #pragma unroll
        for (int k = 0; k < Dk; k++) {
            float v = Bs[k * Pn + tid];
            s = fmaf(v, v, s);
        }
        p2s[tid] = s;
    }
    __syncthreads();

    // ---- Main loop: 8 rows x 8 protos per thread, packed f32x2 FMAs ---------
    unsigned long long acc[8][4];
    #pragma unroll
    for (int r = 0; r < 8; r++)
        #pragma unroll
        for (int j = 0; j < 4; j++) acc[r][j] = 0ull;

    #pragma unroll 8
    for (int k = 0; k < Dk; k++) {
        // a: 8 duplicated row values — warp-broadcast LDS.128 (lanes share addr)
        const float2* ar = &As2[k * AS_STRIDE + ty * 8];
        ulonglong2 a01 = *(const ulonglong2*)(ar + 0);
        ulonglong2 a23 = *(const ulonglong2*)(ar + 2);
        ulonglong2 a45 = *(const ulonglong2*)(ar + 4);
        ulonglong2 a67 = *(const ulonglong2*)(ar + 6);
        // b: 8 protos (4 packed pairs) per lane
        const float* br = &Bs[k * Pn + tx * 8];
        ulonglong2 b01 = *(const ulonglong2*)(br);
        ulonglong2 b23 = *(const ulonglong2*)(br + 4);

        unsigned long long av[8] = {a01.x, a01.y, a23.x, a23.y,
                                    a45.x, a45.y, a67.x, a67.y};
        unsigned long long bv[4] = {b01.x, b01.y, b23.x, b23.y};

        #pragma unroll
        for (int r = 0; r < 8; r++)
            #pragma unroll
            for (int j = 0; j < 4; j++)
                acc[r][j] = ffma2(av[r], bv[j], acc[r][j]);
    }

    // ---- Epilogue: mse -> inv_d, store, warp argmax -------------------------
    const float inv64 = 1.0f / 64.0f;
    const int row0 = blockIdx.x * BM + ty * 8;

    #pragma unroll
    for (int r = 0; r < 8; r++) {
        const int row = row0 + r;
        const float f2 = f2s[ty * 8 + r];
        float vals[8];
        #pragma unroll
        for (int j = 0; j < 4; j++) {
            unsigned int lo = (unsigned int)(acc[r][j] & 0xffffffffull);
            unsigned int hi = (unsigned int)(acc[r][j] >> 32);
            float c0 = __uint_as_float(lo);
            float c1 = __uint_as_float(hi);
            int p0 = tx * 8 + 2 * j;
            float m0 = fmaf(-2.f, c0, f2 + p2s[p0])     * inv64;
            float m1 = fmaf(-2.f, c1, f2 + p2s[p0 + 1]) * inv64;
            vals[2 * j]     = __fdividef(1.f, m0 + EPSV);
            vals[2 * j + 1] = __fdividef(1.f, m1 + EPSV);
        }

        if (inv_out) {
            float* orow = inv_out + (size_t)row * Pn + tx * 8;
            *(float4*)(orow)     = make_float4(vals[0], vals[1], vals[2], vals[3]);
            *(float4*)(orow + 4) = make_float4(vals[4], vals[5], vals[6], vals[7]);
        }

        // local argmax (ascending index, strict > keeps first occurrence)
        float bvv = vals[0];
        int   bi  = tx * 8;
        #pragma unroll
        for (int j = 1; j < 8; j++) {
            if (vals[j] > bvv) { bvv = vals[j]; bi = tx * 8 + j; }
        }
        // warp butterfly; ties -> lower index (matches jnp.argmax)
        #pragma unroll
        for (int off = 16; off > 0; off >>= 1) {
            float ov = __shfl_xor_sync(0xffffffffu, bvv, off);
            int   oi = __shfl_xor_sync(0xffffffffu, bi,  off);
            if (ov > bvv || (ov == bvv && oi < bi)) { bvv = ov; bi = oi; }
        }
        if (tx == 0 && labels_out) {
            if (labels_as_int) ((int*)labels_out)[row] = proto_labels[bi];
            else               labels_out[row] = (float)proto_labels[bi];
        }
    }
}

extern "C" void kernel_launch(void* const* d_in, const int* in_sizes, int n_in,
                              void* d_out, int out_size)
{
    const float* features     = (const float*)d_in[0];
    const float* protos       = (const float*)d_in[1];
    const int*   proto_labels = (const int*)d_in[2];

    const int       P = in_sizes[2];
    const int       D = in_sizes[1] / P;
    const long long N = (long long)in_sizes[0] / D;
    const size_t  npe = (size_t)N * (size_t)P;

    float* inv_out = nullptr;
    float* lab     = nullptr;
    int    lab_int = 0;
    if ((size_t)out_size >= npe) {
        inv_out = (float*)d_out;
        if ((size_t)out_size >= npe + (size_t)N) lab = (float*)d_out + npe;
    } else {
        // output holds only labels
        lab = (float*)d_out;
        lab_int = 1;
    }

    cudaFuncSetAttribute(BaseProtonet_kernel,
                         cudaFuncAttributeMaxDynamicSharedMemorySize, SMEM_BYTES);
    BaseProtonet_kernel<<<(int)(N / BM), 256, SMEM_BYTES>>>(
        features, protos, proto_labels, inv_out, lab, lab_int);
}

// round 3
// speedup vs baseline: 1.9903x; 1.9903x over previous
#include <cuda_runtime.h>
#include <cuda_fp16.h>
#include <cstdint>

// ---------------------------------------------------------------------------
// BaseProtonet via mma.sync (HMMA) — tcgen05 is unavailable (harness PTX target
// is compute_103, no 'a' suffix). 4-pass fp16 hi/lo split => fp32-exact GEMM
// up to accumulation rounding.
// inv_d[N,P] = 1/(||f-p||^2/64 + 1e-5) = 64/(f2+p2-2*cross+64e-5)
// labels[n] = proto_labels[argmax_p inv_d]. N=262144, D=64, P=256.
// Per CTA: 128 rows x 256 protos. 256 threads = 8 warps, 16 rows/warp.
// ---------------------------------------------------------------------------

#define SWZ128(o) ((o) ^ (((o) >> 3) & 0x70))

constexpr int Dk = 64;
constexpr int Pn = 256;
constexpr int BM = 128;
constexpr int THREADS = 256;

constexpr int OFF_AHI = 0;          // 128 rows x 128B = 16384
constexpr int OFF_ALO = 16384;      // 16384
constexpr int OFF_BHI = 32768;      // 256 rows x 128B = 32768
constexpr int OFF_BLO = 65536;      // 32768
constexpr int OFF_P2  = 98304;      // 256*4
constexpr int OFF_F2  = 99328;      // 128*4
constexpr int SMEM_BYTES = 99840;   // < 113KB -> 2 CTAs/SM

__device__ __forceinline__ uint32_t smem_u32(const void* p) {
    uint32_t a;
    asm("{ .reg .u64 t; cvta.to.shared.u64 t, %1; cvt.u32.u64 %0, t; }" : "=r"(a) : "l"(p));
    return a;
}
__device__ __forceinline__ void ldsm_x4(uint32_t r[4], uint32_t addr) {
    asm volatile("ldmatrix.sync.aligned.m8n8.x4.shared.b16 {%0,%1,%2,%3}, [%4];"
                 : "=r"(r[0]), "=r"(r[1]), "=r"(r[2]), "=r"(r[3]) : "r"(addr));
}
__device__ __forceinline__ void mma16816(float c[4], const uint32_t a[4],
                                         uint32_t b0, uint32_t b1) {
    asm volatile("mma.sync.aligned.m16n8k16.row.col.f32.f16.f16.f32 "
                 "{%0,%1,%2,%3}, {%4,%5,%6,%7}, {%8,%9}, {%0,%1,%2,%3};"
                 : "+f"(c[0]), "+f"(c[1]), "+f"(c[2]), "+f"(c[3])
                 : "r"(a[0]), "r"(a[1]), "r"(a[2]), "r"(a[3]), "r"(b0), "r"(b1));
}
__device__ __forceinline__ uint32_t pack2(float x, float y) {
    __half hx = __float2half_rn(x), hy = __float2half_rn(y);
    return (uint32_t)__half_as_ushort(hx) | ((uint32_t)__half_as_ushort(hy) << 16);
}

__global__ void __launch_bounds__(THREADS, 2)
BaseProtonet_hmma(const float* __restrict__ features,
                  const float* __restrict__ protos,
                  const int*   __restrict__ proto_labels,
                  float* __restrict__ inv_out,
                  float* __restrict__ labels_out,
                  int labels_as_int)
{
    extern __shared__ char smem[];
    const uint32_t sbase = smem_u32(smem);
    const int tid  = threadIdx.x;
    const int wid  = tid >> 5;
    const int lane = tid & 31;

    float* p2s = (float*)(smem + OFF_P2);
    float* f2s = (float*)(smem + OFF_F2);

    const float* fb = features + (size_t)blockIdx.x * BM * Dk;

    // ---- Convert A tile to fp16 hi/lo into SW128 smem ----------------------
    {
        const float4* f4p = (const float4*)fb;
        #pragma unroll
        for (int i = 0; i < (BM * Dk / 4) / THREADS; i++) {   // 8 iters
            int f4  = tid + i * THREADS;
            int row = f4 >> 4, k4 = f4 & 15;
            float4 v = f4p[f4];
            float hx = __half2float(__float2half_rn(v.x));
            float hy = __half2float(__float2half_rn(v.y));
            float hz = __half2float(__float2half_rn(v.z));
            float hw = __half2float(__float2half_rn(v.w));
            uint2 hi = make_uint2(pack2(v.x, v.y), pack2(v.z, v.w));
            uint2 lo = make_uint2(pack2(v.x - hx, v.y - hy), pack2(v.z - hz, v.w - hw));
            uint32_t off = SWZ128((uint32_t)(row * 128 + k4 * 8));
            *(uint2*)(smem + OFF_AHI + off) = hi;
            *(uint2*)(smem + OFF_ALO + off) = lo;
        }
    }
    // ---- Convert B (all protos) -------------------------------------------
    {
        const float4* p4p = (const float4*)protos;
        #pragma unroll
        for (int i = 0; i < (Pn * Dk / 4) / THREADS; i++) {   // 16 iters
            int f4  = tid + i * THREADS;
            int row = f4 >> 4, k4 = f4 & 15;
            float4 v = p4p[f4];
            float hx = __half2float(__float2half_rn(v.x));
            float hy = __half2float(__float2half_rn(v.y));
            float hz = __half2float(__float2half_rn(v.z));
            float hw = __half2float(__float2half_rn(v.w));
            uint2 hi = make_uint2(pack2(v.x, v.y), pack2(v.z, v.w));
            uint2 lo = make_uint2(pack2(v.x - hx, v.y - hy), pack2(v.z - hz, v.w - hw));
            uint32_t off = SWZ128((uint32_t)(row * 128 + k4 * 8));
            *(uint2*)(smem + OFF_BHI + off) = hi;
            *(uint2*)(smem + OFF_BLO + off) = lo;
        }
    }
    // ---- Norms (fp32, L1-warm re-read) -------------------------------------
    if (tid < BM) {
        const float4* fr = (const float4*)fb + tid * 16;
        float s = 0.f;
        #pragma unroll
        for (int j = 0; j < 16; j++) {
            float4 v = fr[j];
            s = fmaf(v.x, v.x, s); s = fmaf(v.y, v.y, s);
            s = fmaf(v.z, v.z, s); s = fmaf(v.w, v.w, s);
        }
        f2s[tid] = s;
    }
    {
        const float4* pr = (const float4*)protos + tid * 16;
        float q = 0.f;
        #pragma unroll
        for (int j = 0; j < 16; j++) {
            float4 v = pr[j];
            q = fmaf(v.x, v.x, q); q = fmaf(v.y, v.y, q);
            q = fmaf(v.z, v.z, q); q = fmaf(v.w, v.w, q);
        }
        p2s[tid] = q;
    }
    __syncthreads();

    // ---- Load A fragments (both matrices, all 4 k-steps) --------------------
    const int wr0 = wid * 16;
    uint32_t ahi[4][4], alo[4][4];
    {
        int arow  = wr0 + (lane & 15);
        int achnk = (lane >> 4);                 // 0 or 1
        #pragma unroll
        for (int ks = 0; ks < 4; ks++) {
            uint32_t off = SWZ128((uint32_t)(arow * 128 + (2 * ks + achnk) * 16));
            ldsm_x4(ahi[ks], sbase + OFF_AHI + off);
            ldsm_x4(alo[ks], sbase + OFF_ALO + off);
        }
    }

    const int g = lane >> 2;
    const float srowA = f2s[wr0 + g]     + 64.f * 1e-5f;
    const float srowB = f2s[wr0 + g + 8] + 64.f * 1e-5f;

    float bestA = -1e30f, bestB = -1e30f;
    int   idxA  = 0,      idxB  = 0;

    const size_t row0  = (size_t)blockIdx.x * BM;
    const size_t rowA  = row0 + wr0 + g;
    const size_t rowB  = rowA + 8;

    // B-fragment lane addressing (constant parts)
    const int bn_lane = (lane & 7) + ((lane >> 4) & 1) * 8;
    const int bc_lane = (lane >> 3) & 1;

    #pragma unroll
    for (int cb = 0; cb < 4; cb++) {             // 4 col-blocks of 64 protos
        float acc[8][4];
        #pragma unroll
        for (int t = 0; t < 8; t++)
            #pragma unroll
            for (int j = 0; j < 4; j++) acc[t][j] = 0.f;

        #pragma unroll
        for (int ks = 0; ks < 4; ks++) {
            #pragma unroll
            for (int tp = 0; tp < 4; tp++) {     // tile pairs (2 n8-tiles each)
                int n     = cb * 64 + tp * 16 + bn_lane;
                int chunk = 2 * ks + bc_lane;
                uint32_t off = SWZ128((uint32_t)(n * 128 + chunk * 16));
                uint32_t bhi[4], blo[4];
                ldsm_x4(bhi, sbase + OFF_BHI + off);
                ldsm_x4(blo, sbase + OFF_BLO + off);
                const int t0 = tp * 2, t1 = tp * 2 + 1;
                mma16816(acc[t0], ahi[ks], bhi[0], bhi[1]);
                mma16816(acc[t1], ahi[ks], bhi[2], bhi[3]);
                mma16816(acc[t0], ahi[ks], blo[0], blo[1]);
                mma16816(acc[t1], ahi[ks], blo[2], blo[3]);
                mma16816(acc[t0], alo[ks], bhi[0], bhi[1]);
                mma16816(acc[t1], alo[ks], bhi[2], bhi[3]);
                mma16816(acc[t0], alo[ks], blo[0], blo[1]);
                mma16816(acc[t1], alo[ks], blo[2], blo[3]);
            }
        }

        // ---- Epilogue for this col-block -----------------------------------
        #pragma unroll
        for (int t = 0; t < 8; t++) {
            const int col = cb * 64 + t * 8 + (lane & 3) * 2;
            float2 p2v = *(const float2*)&p2s[col];
            float v0 = __fdividef(64.f, fmaf(-2.f, acc[t][0], srowA + p2v.x));
            float v1 = __fdividef(64.f, fmaf(-2.f, acc[t][1], srowA + p2v.y));
            float v2 = __fdividef(64.f, fmaf(-2.f, acc[t][2], srowB + p2v.x));
            float v3 = __fdividef(64.f, fmaf(-2.f, acc[t][3], srowB + p2v.y));
            if (inv_out) {
                *(float2*)&inv_out[rowA * Pn + col] = make_float2(v0, v1);
                *(float2*)&inv_out[rowB * Pn + col] = make_float2(v2, v3);
            }
            if (v0 > bestA) { bestA = v0; idxA = col; }
            if (v1 > bestA) { bestA = v1; idxA = col + 1; }
            if (v2 > bestB) { bestB = v2; idxB = col; }
            if (v3 > bestB) { bestB = v3; idxB = col + 1; }
        }
    }

    // ---- Quad argmax reduction (lanes sharing a row), first-index ties -----
    #pragma unroll
    for (int off = 1; off <= 2; off <<= 1) {
        float ov = __shfl_xor_sync(0xffffffffu, bestA, off);
        int   oi = __shfl_xor_sync(0xffffffffu, idxA,  off);
        if (ov > bestA || (ov == bestA && oi < idxA)) { bestA = ov; idxA = oi; }
        float pv = __shfl_xor_sync(0xffffffffu, bestB, off);
        int   pi = __shfl_xor_sync(0xffffffffu, idxB,  off);
        if (pv > bestB || (pv == bestB && pi < idxB)) { bestB = pv; idxB = pi; }
    }
    if ((lane & 3) == 0 && labels_out) {
        int labA = proto_labels[idxA];
        int labB = proto_labels[idxB];
        if (labels_as_int) {
            ((int*)labels_out)[rowA] = labA;
            ((int*)labels_out)[rowB] = labB;
        } else {
            labels_out[rowA] = (float)labA;
            labels_out[rowB] = (float)labB;
        }
    }
}

extern "C" void kernel_launch(void* const* d_in, const int* in_sizes, int n_in,
                              void* d_out, int out_size)
{
    const float* features     = (const float*)d_in[0];
    const float* protos       = (const float*)d_in[1];
    const int*   proto_labels = (const int*)d_in[2];

    const int       P = in_sizes[2];
    const int       D = in_sizes[1] / P;
    const long long N = (long long)in_sizes[0] / D;
    const size_t  npe = (size_t)N * (size_t)P;

    float* inv_out = nullptr;
    float* lab     = nullptr;
    int    lab_int = 0;
    if ((size_t)out_size >= npe) {
        inv_out = (float*)d_out;
        if ((size_t)out_size >= npe + (size_t)N) lab = (float*)d_out + npe;
    } else {
        lab = (float*)d_out;
        lab_int = 1;
    }

    cudaFuncSetAttribute(BaseProtonet_hmma,
                         cudaFuncAttributeMaxDynamicSharedMemorySize, SMEM_BYTES);
    BaseProtonet_hmma<<<(int)(N / BM), THREADS, SMEM_BYTES>>>(
        features, protos, proto_labels, inv_out, lab, lab_int);
}